// round 8
// baseline (speedup 1.0000x reference)
#include <cuda_runtime.h>
#include <cstdint>

// Problem shape (fixed per reference)
#define B   16
#define T   32
#define C   131072            // 128*32*32
#define C4  (C/4)             // 32768 float4 per b
#define HIST_T_STRIDE4 ((size_t)B * C4)   // float4 stride between timesteps
#define CHUNK4 256            // float4 per block
#define CHUNKS_PER_B (C4 / CHUNK4)        // 128
#define GROUP_B 8                          // b's per phase (8*16.8MB ~= L2)
#define GROUP_GRID (GROUP_B * CHUNKS_PER_B)  // 1024 blocks per phase kernel
#define INV_SCALE 0.2f

// Deterministic scratch (no atomics anywhere).
__device__ float g_partials[B * T * CHUNKS_PER_B];   // 256 KB

// ld.global.cg: L2-cached, L1-bypassed — keeps streamed history L2-resident.
__device__ __forceinline__ float4 ldcg4(const float4* p) {
    float4 v;
    asm volatile("ld.global.cg.v4.f32 {%0,%1,%2,%3}, [%4];"
                 : "=f"(v.x), "=f"(v.y), "=f"(v.z), "=f"(v.w) : "l"(p));
    return v;
}

// st.global.cs: evict-first store — output must not displace resident history.
__device__ __forceinline__ void stcs4(float4* p, float4 v) {
    asm volatile("st.global.cs.v4.f32 [%0], {%1,%2,%3,%4};"
                 :: "l"(p), "f"(v.x), "f"(v.y), "f"(v.z), "f"(v.w) : "memory");
}

// ---------------------------------------------------------------------------
// Phase kernel S: partial[b][t][chunk] = dot(curr[b][chunk], hist[t][b][chunk])
// for b in [b0, b0+GROUP_B). 32 front-batched independent loads per thread
// (per-thread MLP beats occupancy here — R3 post-mortem). ld.cg leaves this
// group's 134 MB of history resident in L2 for the matching O phase.
// ---------------------------------------------------------------------------
__global__ void __launch_bounds__(256, 4)
scores_kernel(const float4* __restrict__ curr, const float4* __restrict__ hist,
              int b0) {
    const int b     = b0 + (blockIdx.x >> 7);        // / CHUNKS_PER_B
    const int chunk = blockIdx.x & (CHUNKS_PER_B - 1);
    const int k     = chunk * CHUNK4 + threadIdx.x;
    const int lane  = threadIdx.x & 31;
    const int warp  = threadIdx.x >> 5;

    const float4 q = curr[(size_t)b * C4 + k];
    const float4* hp = hist + (size_t)b * C4 + k;

    float acc[T];
    #pragma unroll
    for (int t = 0; t < T; t++) {
        float4 hv = ldcg4(hp + (size_t)t * HIST_T_STRIDE4);
        acc[t] = q.x * hv.x + q.y * hv.y + q.z * hv.z + q.w * hv.w;
    }

    // Multi-value butterfly: after log2(32) halving steps, lane l holds the
    // warp-wide sum for timestep l. 31 shuffles per thread total.
    #pragma unroll
    for (int w = 16; w >= 1; w >>= 1) {
        const bool upper = (lane & w) != 0;
        #pragma unroll
        for (int i = 0; i < 16; i++) {
            if (i < w) {
                float send = upper ? acc[i] : acc[i + w];
                float recv = __shfl_xor_sync(0xffffffffu, send, w);
                acc[i] = (upper ? acc[i + w] : acc[i]) + recv;
            }
        }
    }

    __shared__ float s_part[8][T];
    s_part[warp][lane] = acc[0];
    __syncthreads();

    if (threadIdx.x < T) {
        float s = 0.0f;
        #pragma unroll
        for (int wr = 0; wr < 8; wr++) s += s_part[wr][threadIdx.x];
        g_partials[(b * T + threadIdx.x) * CHUNKS_PER_B + chunk] = s;
    }
}

// ---------------------------------------------------------------------------
// Phase kernel O: every block recomputes its b's softmax from g_partials
// (16 KB L2 read, fixed order -> deterministic), then
// out[b][k] = sum_t w[t] * hist[t][b][k].
// Reversed block mapping within the group: first-scheduled O blocks re-read
// the history S just streamed (L2 tail alignment).
// ---------------------------------------------------------------------------
__global__ void __launch_bounds__(256, 4)
out_kernel(const float4* __restrict__ hist, float4* __restrict__ out, int b0) {
    const int rb    = (GROUP_GRID - 1) - blockIdx.x;   // in-group reversal
    const int b     = b0 + (rb >> 7);
    const int k     = (rb & (CHUNKS_PER_B - 1)) * CHUNK4 + threadIdx.x;
    const int lane  = threadIdx.x & 31;
    const int warp  = threadIdx.x >> 5;

    // ---- per-block softmax recompute (same fixed order in every block) ----
    __shared__ float sc[T];
    __shared__ float w[T];
    #pragma unroll
    for (int i = 0; i < 4; i++) {
        const int t = warp + 8 * i;
        const float* p = &g_partials[(b * T + t) * CHUNKS_PER_B];
        float s = p[lane] + p[lane + 32] + p[lane + 64] + p[lane + 96];
        #pragma unroll
        for (int ww = 16; ww >= 1; ww >>= 1)
            s += __shfl_xor_sync(0xffffffffu, s, ww);
        if (lane == 0) sc[t] = s * INV_SCALE;
    }
    __syncthreads();
    if (warp == 0) {
        float v = sc[lane];
        float m = v;
        #pragma unroll
        for (int ww = 16; ww >= 1; ww >>= 1)
            m = fmaxf(m, __shfl_xor_sync(0xffffffffu, m, ww));
        float e = expf(v - m);
        float z = e;
        #pragma unroll
        for (int ww = 16; ww >= 1; ww >>= 1)
            z += __shfl_xor_sync(0xffffffffu, z, ww);
        w[lane] = e / z;
    }
    __syncthreads();

    // ---- weighted sum: 32 front-batched strided float4 loads ----
    const float4* hp = hist + (size_t)b * C4 + k;
    float4 acc = make_float4(0.f, 0.f, 0.f, 0.f);
    #pragma unroll
    for (int t = 0; t < T; t++) {
        float4 hv = ldcg4(hp + (size_t)t * HIST_T_STRIDE4);
        float wt = w[t];
        acc.x += wt * hv.x;
        acc.y += wt * hv.y;
        acc.z += wt * hv.z;
        acc.w += wt * hv.w;
    }
    stcs4(out + (size_t)b * C4 + k, acc);
}

// ---------------------------------------------------------------------------
// Group-phased schedule: S(g) streams ~134 MB into L2, O(g) consumes it while
// still resident. 4 launches total.
// ---------------------------------------------------------------------------
extern "C" void kernel_launch(void* const* d_in, const int* in_sizes, int n_in,
                              void* d_out, int out_size) {
    const float4* curr = (const float4*)d_in[0];   // h_current [16,128,32,32]
    const float4* hist = (const float4*)d_in[1];   // h_history [32,16,128,32,32]
    float4* out = (float4*)d_out;

    scores_kernel<<<GROUP_GRID, 256>>>(curr, hist, 0);
    out_kernel   <<<GROUP_GRID, 256>>>(hist, out, 0);
    scores_kernel<<<GROUP_GRID, 256>>>(curr, hist, GROUP_B);
    out_kernel   <<<GROUP_GRID, 256>>>(hist, out, GROUP_B);
}